// round 14
// baseline (speedup 1.0000x reference)
#include <cuda_runtime.h>
#include <cuda_fp16.h>
#include <cuda_bf16.h>
#include <cstdint>
#include <cstring>

#define DIM   64
#define MAX_N 50000
#define CAP   64      // max degree bucket (deg ~ Poisson(16); P(>64) ~ 1e-18)
#define TM    64      // rows per transform block (shrunk so xs+wt fit in 35KB)

#define XS_STRIDE 69  // odd -> conflict-free scalar broadcast reads
#define WT_STRIDE 68  // %4==0 -> aligned float4 reads, contiguous per phase

// Scratch (allocation-free rule: __device__ globals; zero-init at module load)
__device__ __half2 g_xwh[MAX_N * (DIM / 2)];    // x @ W^T in fp16, 6.4 MB
__device__ int     g_cnt[MAX_N];                // per-row edge count; INVARIANT:
                                                // all-zero at entry (gather resets)
__device__ int     g_slots[MAX_N * CAP];        // per-row col lists, 12.8 MB

__device__ __forceinline__ unsigned h2_bits(__half2 h) {
    unsigned u;
    memcpy(&u, &h, 4);
    return u;
}

// ---------------------------------------------------------------------------
// Kernel 1 (fused): blocks [0, tblocks) run transform (xw = x @ W^T, fp16
// output), blocks [tblocks, ...) run fill (bucket edges by destination row).
// No prep kernel: each transform block stages its own W^T; fill blocks detect
// the edge dtype; counters are pre-zeroed by the self-restoring invariant.
// Shared = xs 17.7KB + wt 17.4KB = 35.1KB (keeps 6 blocks/SM residency).
// ---------------------------------------------------------------------------
__global__ void tf_kernel(const float* __restrict__ x,
                          const float* __restrict__ W,
                          const void* __restrict__ ei_raw,
                          int n, int n_e, int tblocks) {
    __shared__ float xs[DIM][XS_STRIDE];   // xs[k][r] (k-major x tile)
    __shared__ float wt[DIM][WT_STRIDE];   // wt[k][j] = W[j][k] (k-major W^T)

    if (blockIdx.x < tblocks) {
        // ---------------- transform: 2 rows x 8 cols per thread -------------
        int tid  = threadIdx.x;
        int row0 = blockIdx.x * TM;

        // Stage W^T: coalesced float4 reads of W[j][k], transpose store.
        for (int i = tid; i < DIM * (DIM / 4); i += 256) {
            int j  = i >> 4;          // 0..63 (W row)
            int kq = i & 15;          // 0..15 (float4 over k)
            float4 v = ((const float4*)W)[i];
            wt[kq * 4 + 0][j] = v.x;
            wt[kq * 4 + 1][j] = v.y;
            wt[kq * 4 + 2][j] = v.z;
            wt[kq * 4 + 3][j] = v.w;
        }

        // Stage x tile transposed: xs[k][r]
        for (int i = tid; i < TM * (DIM / 4); i += 256) {
            int r  = i >> 4;          // 0..63
            int kq = i & 15;          // 0..15
            int row = row0 + r;
            float4 v = (row < n) ? ((const float4*)x)[row * (DIM / 4) + kq]
                                 : make_float4(0.f, 0.f, 0.f, 0.f);
            xs[kq * 4 + 0][r] = v.x;
            xs[kq * 4 + 1][r] = v.y;
            xs[kq * 4 + 2][r] = v.z;
            xs[kq * 4 + 3][r] = v.w;
        }
        __syncthreads();

        int ty = tid >> 3;        // 0..31
        int tx = tid & 7;         // 0..7
        int r0 = ty * 2;

        float acc[2][8];
#pragma unroll
        for (int i = 0; i < 2; i++)
#pragma unroll
            for (int j = 0; j < 8; j++) acc[i][j] = 0.f;

#pragma unroll 8
        for (int k = 0; k < DIM; k++) {
            float av0 = xs[k][r0 + 0];
            float av1 = xs[k][r0 + 1];
            float4 wa = *(const float4*)&wt[k][tx * 8];
            float4 wb = *(const float4*)&wt[k][tx * 8 + 4];
            float wv[8] = {wa.x, wa.y, wa.z, wa.w, wb.x, wb.y, wb.z, wb.w};
#pragma unroll
            for (int j = 0; j < 8; j++) {
                acc[0][j] += av0 * wv[j];
                acc[1][j] += av1 * wv[j];
            }
        }

        // Epilogue: pack 8 fp32 -> 4 half2 -> one 16B store per row.
        uint4* xw_u4 = reinterpret_cast<uint4*>(g_xwh);
#pragma unroll
        for (int i = 0; i < 2; i++) {
            int row = row0 + r0 + i;
            if (row < n) {
                uint4 p;
                p.x = h2_bits(__floats2half2_rn(acc[i][0], acc[i][1]));
                p.y = h2_bits(__floats2half2_rn(acc[i][2], acc[i][3]));
                p.z = h2_bits(__floats2half2_rn(acc[i][4], acc[i][5]));
                p.w = h2_bits(__floats2half2_rn(acc[i][6], acc[i][7]));
                xw_u4[row * 8 + tx] = p;
            }
        }
    } else {
        // ---------------- fill: bucket edges (int atomics only) -------------
        __shared__ int s_mode;
        // Detect edge dtype: first 8 int64 reads are in-bounds under both
        // interpretations (E int64 == 2E int32 bytes).
        int bad = 0;
        if (threadIdx.x < 8) {
            int idx = (threadIdx.x < n_e) ? threadIdx.x : 0;
            long long v = ((const long long*)ei_raw)[idx];
            bad = (v < 0 || v >= (long long)n) ? 1 : 0;
        }
        if (threadIdx.x < 32) {
            unsigned msk = __ballot_sync(0xffffffffu, bad);
            if (threadIdx.x == 0) s_mode = (msk != 0) ? 1 : 0;
        }
        __syncthreads();
        int mode = s_mode;   // 1 = int32, 0 = int64

        int e = (blockIdx.x - tblocks) * blockDim.x + threadIdx.x;
        if (e >= n_e) return;

        int row, col;
        if (mode) {
            const int* p = (const int*)ei_raw;
            row = p[e];
            col = p[n_e + e];
        } else {
            const long long* p = (const long long*)ei_raw;
            row = (int)p[e];
            col = (int)p[n_e + e];
        }
        if ((unsigned)row >= (unsigned)n || (unsigned)col >= (unsigned)n) return;

        int pos = atomicAdd(&g_cnt[row], 1);
        if (pos < CAP) g_slots[row * CAP + pos] = col;
    }
}

// ---------------------------------------------------------------------------
// Kernel 2: gather — one warp per row, lane owns 2 output dims (one half2).
// One 128B line per edge-row read. Unroll 8 with 4 independent fp32
// accumulator chains; slot indices fetched as 2 x int4; fused /deg + b.
// Resets g_cnt[w] after use (self-restoring invariant for graph replay).
// ---------------------------------------------------------------------------
__global__ void gather_kernel(const float* __restrict__ bias,
                              float* __restrict__ out, int n) {
    int w    = (blockIdx.x * blockDim.x + threadIdx.x) >> 5;
    int lane = threadIdx.x & 31;
    if (w >= n) return;

    int deg = g_cnt[w];
    int m = deg < CAP ? deg : CAP;

    const __half2* xwh = g_xwh;
    const int*     sl  = g_slots + (size_t)w * CAP;
    const int4*    sl4 = (const int4*)sl;

    float2 a0 = make_float2(0.f, 0.f);
    float2 a1 = make_float2(0.f, 0.f);
    float2 a2 = make_float2(0.f, 0.f);
    float2 a3 = make_float2(0.f, 0.f);

    int e = 0;
    for (; e + 8 <= m; e += 8) {
        int4 ca = sl4[(e >> 2) + 0];
        int4 cb = sl4[(e >> 2) + 1];
        float2 v0 = __half22float2(xwh[ca.x * 32 + lane]);
        float2 v1 = __half22float2(xwh[ca.y * 32 + lane]);
        float2 v2 = __half22float2(xwh[ca.z * 32 + lane]);
        float2 v3 = __half22float2(xwh[ca.w * 32 + lane]);
        float2 v4 = __half22float2(xwh[cb.x * 32 + lane]);
        float2 v5 = __half22float2(xwh[cb.y * 32 + lane]);
        float2 v6 = __half22float2(xwh[cb.z * 32 + lane]);
        float2 v7 = __half22float2(xwh[cb.w * 32 + lane]);
        a0.x += v0.x + v4.x;  a0.y += v0.y + v4.y;
        a1.x += v1.x + v5.x;  a1.y += v1.y + v5.y;
        a2.x += v2.x + v6.x;  a2.y += v2.y + v6.y;
        a3.x += v3.x + v7.x;  a3.y += v3.y + v7.y;
    }
    for (; e + 2 <= m; e += 2) {
        int c0 = sl[e], c1 = sl[e + 1];
        float2 v0 = __half22float2(xwh[c0 * 32 + lane]);
        float2 v1 = __half22float2(xwh[c1 * 32 + lane]);
        a0.x += v0.x; a0.y += v0.y;
        a1.x += v1.x; a1.y += v1.y;
    }
    if (e < m) {
        int c = sl[e];
        float2 v = __half22float2(xwh[c * 32 + lane]);
        a2.x += v.x; a2.y += v.y;
    }

    float inv = 1.f / ((float)deg + 1e-6f);
    float2 bb = ((const float2*)bias)[lane];
    float2 r;
    r.x = ((a0.x + a1.x) + (a2.x + a3.x)) * inv + bb.x;
    r.y = ((a0.y + a1.y) + (a2.y + a3.y)) * inv + bb.y;
    ((float2*)out)[(size_t)w * 32 + lane] = r;

    // Reset counter for the next graph replay. All lanes loaded g_cnt[w]
    // above; syncwarp orders those reads before lane 0's store.
    __syncwarp();
    if (lane == 0) g_cnt[w] = 0;
}

// ---------------------------------------------------------------------------
extern "C" void kernel_launch(void* const* d_in, const int* in_sizes, int n_in,
                              void* d_out, int out_size) {
    const float* x  = (const float*)d_in[0];
    const void*  ei = d_in[1];
    const float* W  = (const float*)d_in[2];
    const float* b  = (const float*)d_in[3];
    float*       out = (float*)d_out;

    int n  = in_sizes[0] / DIM;   // 50000
    int ne = in_sizes[1] / 2;     // 800000 (element count is 2E for both dtypes)

    int tblocks = (n + TM - 1) / TM;            // 782 transform blocks
    int fblocks = (ne + 255) / 256;             // 3125 fill blocks
    tf_kernel<<<tblocks + fblocks, 256>>>(x, W, ei, n, ne, tblocks);

    {
        long long thr = (long long)n * 32;
        gather_kernel<<<(int)((thr + 255) / 256), 256>>>(b, out, n);
    }
}

// round 15
// speedup vs baseline: 1.3356x; 1.3356x over previous
#include <cuda_runtime.h>
#include <cuda_fp16.h>
#include <cuda_bf16.h>
#include <cstdint>
#include <cstring>

#define DIM   64
#define MAX_N 50000
#define CAP   64      // max degree bucket (deg ~ Poisson(16); P(>64) ~ 1e-18)
#define TM    128     // rows per transform block

// Scratch (allocation-free rule: __device__ globals; zero-init at module load)
__device__ __half2 g_xwh[MAX_N * (DIM / 2)];    // x @ W^T in fp16, 6.4 MB
__device__ float4  g_wt4[DIM * DIM / 4];        // W^T (k-major), 16 KB
__device__ int     g_cnt[MAX_N];                // per-row edge count; INVARIANT:
                                                // all-zero at entry (gather resets)
__device__ int     g_slots[MAX_N * CAP];        // per-row col lists, 12.8 MB
__device__ int     g_mode;                      // 0 = int64 edge_index, 1 = int32

__device__ __forceinline__ unsigned h2_bits(__half2 h) {
    unsigned u;
    memcpy(&u, &h, 4);
    return u;
}

// ---------------------------------------------------------------------------
// Kernel 1: prep (lite) — transpose W + detect edge dtype. Counter zeroing
// is handled by gather's self-restoring reset, so grid is only 16 blocks.
// ---------------------------------------------------------------------------
__global__ void prep_kernel(const float* __restrict__ W,
                            const void* __restrict__ ei, int n_e, int n) {
    __shared__ int s_bad;
    int i = blockIdx.x * blockDim.x + threadIdx.x;
    if (i < DIM * DIM) {
        int j = i / DIM, k = i % DIM;             // W[j][k], row-major
        reinterpret_cast<float*>(g_wt4)[k * DIM + j] = W[i];
    }
    if (blockIdx.x == 0) {
        if (threadIdx.x == 0) s_bad = 0;
        __syncthreads();
        // First 64 int64 reads are in-bounds under both dtype interpretations.
        int cnt = n_e < 64 ? n_e : 64;
        if (threadIdx.x < cnt) {
            long long v = ((const long long*)ei)[threadIdx.x];
            if (v < 0 || v >= (long long)n) atomicOr(&s_bad, 1);
        }
        __syncthreads();
        if (threadIdx.x == 0) g_mode = s_bad;     // 1 = int32, 0 = int64
    }
}

// ---------------------------------------------------------------------------
// Kernel 2 (fused): blocks [0, tblocks) run transform (xw = x @ W^T, stored
// fp16), blocks [tblocks, ...) run fill (bucket edges by destination row).
// NOTE: static smem kept at 34 KB (xs only; W^T read from global g_wt4) —
// larger smem throttles fill-block residency and regresses badly (R6-R8, R13).
// ---------------------------------------------------------------------------
__global__ void tf_kernel(const float* __restrict__ x,
                          const void* __restrict__ ei_raw,
                          int n, int n_e, int tblocks) {
    __shared__ float xs[DIM][TM + 5];   // stride 133 floats (odd), 34 KB

    if (blockIdx.x < tblocks) {
        // ---------------- transform: 4x8 register tile per thread -----------
        int tid  = threadIdx.x;
        int row0 = blockIdx.x * TM;

        for (int i = tid; i < TM * (DIM / 4); i += 256) {
            int r  = i / (DIM / 4);
            int kq = i % (DIM / 4);
            int row = row0 + r;
            float4 v = (row < n) ? ((const float4*)x)[row * (DIM / 4) + kq]
                                 : make_float4(0.f, 0.f, 0.f, 0.f);
            xs[kq * 4 + 0][r] = v.x;
            xs[kq * 4 + 1][r] = v.y;
            xs[kq * 4 + 2][r] = v.z;
            xs[kq * 4 + 3][r] = v.w;
        }
        __syncthreads();

        int ty = tid >> 3;        // 0..31
        int tx = tid & 7;         // 0..7
        int r0 = ty * 4;

        float acc[4][8];
#pragma unroll
        for (int i = 0; i < 4; i++)
#pragma unroll
            for (int j = 0; j < 8; j++) acc[i][j] = 0.f;

#pragma unroll 8
        for (int k = 0; k < DIM; k++) {
            float av[4];
            av[0] = xs[k][r0 + 0];
            av[1] = xs[k][r0 + 1];
            av[2] = xs[k][r0 + 2];
            av[3] = xs[k][r0 + 3];
            float4 w0 = g_wt4[k * (DIM / 4) + tx * 2];
            float4 w1 = g_wt4[k * (DIM / 4) + tx * 2 + 1];
            float wv[8] = {w0.x, w0.y, w0.z, w0.w, w1.x, w1.y, w1.z, w1.w};
#pragma unroll
            for (int i = 0; i < 4; i++)
#pragma unroll
                for (int j = 0; j < 8; j++)
                    acc[i][j] += av[i] * wv[j];
        }

        // Epilogue: pack 8 fp32 -> 4 half2 -> one 16B store per row.
        uint4* xw_u4 = reinterpret_cast<uint4*>(g_xwh);
#pragma unroll
        for (int i = 0; i < 4; i++) {
            int row = row0 + r0 + i;
            if (row < n) {
                uint4 p;
                p.x = h2_bits(__floats2half2_rn(acc[i][0], acc[i][1]));
                p.y = h2_bits(__floats2half2_rn(acc[i][2], acc[i][3]));
                p.z = h2_bits(__floats2half2_rn(acc[i][4], acc[i][5]));
                p.w = h2_bits(__floats2half2_rn(acc[i][6], acc[i][7]));
                xw_u4[row * 8 + tx] = p;
            }
        }
    } else {
        // ---------------- fill: bucket edges (int atomics only) -------------
        int e = (blockIdx.x - tblocks) * blockDim.x + threadIdx.x;
        if (e >= n_e) return;

        int row, col;
        if (g_mode) {
            const int* p = (const int*)ei_raw;
            row = p[e];
            col = p[n_e + e];
        } else {
            const long long* p = (const long long*)ei_raw;
            row = (int)p[e];
            col = (int)p[n_e + e];
        }
        if ((unsigned)row >= (unsigned)n || (unsigned)col >= (unsigned)n) return;

        int pos = atomicAdd(&g_cnt[row], 1);
        if (pos < CAP) g_slots[row * CAP + pos] = col;
    }
}

// ---------------------------------------------------------------------------
// Kernel 3: gather — one warp per row, lane owns 2 output dims (one half2).
// One 128B line per edge-row read. Unroll 8 with 4 independent fp32
// accumulator chains; slot indices fetched as 2 x int4; fused /deg + b.
// Resets g_cnt[w] after use (self-restoring invariant for graph replay).
// ---------------------------------------------------------------------------
__global__ void gather_kernel(const float* __restrict__ bias,
                              float* __restrict__ out, int n) {
    int w    = (blockIdx.x * blockDim.x + threadIdx.x) >> 5;
    int lane = threadIdx.x & 31;
    if (w >= n) return;

    int deg = g_cnt[w];
    int m = deg < CAP ? deg : CAP;

    const __half2* xwh = g_xwh;
    const int*     sl  = g_slots + (size_t)w * CAP;
    const int4*    sl4 = (const int4*)sl;

    float2 a0 = make_float2(0.f, 0.f);
    float2 a1 = make_float2(0.f, 0.f);
    float2 a2 = make_float2(0.f, 0.f);
    float2 a3 = make_float2(0.f, 0.f);

    int e = 0;
    for (; e + 8 <= m; e += 8) {
        int4 ca = sl4[(e >> 2) + 0];
        int4 cb = sl4[(e >> 2) + 1];
        float2 v0 = __half22float2(xwh[ca.x * 32 + lane]);
        float2 v1 = __half22float2(xwh[ca.y * 32 + lane]);
        float2 v2 = __half22float2(xwh[ca.z * 32 + lane]);
        float2 v3 = __half22float2(xwh[ca.w * 32 + lane]);
        float2 v4 = __half22float2(xwh[cb.x * 32 + lane]);
        float2 v5 = __half22float2(xwh[cb.y * 32 + lane]);
        float2 v6 = __half22float2(xwh[cb.z * 32 + lane]);
        float2 v7 = __half22float2(xwh[cb.w * 32 + lane]);
        a0.x += v0.x + v4.x;  a0.y += v0.y + v4.y;
        a1.x += v1.x + v5.x;  a1.y += v1.y + v5.y;
        a2.x += v2.x + v6.x;  a2.y += v2.y + v6.y;
        a3.x += v3.x + v7.x;  a3.y += v3.y + v7.y;
    }
    for (; e + 2 <= m; e += 2) {
        int c0 = sl[e], c1 = sl[e + 1];
        float2 v0 = __half22float2(xwh[c0 * 32 + lane]);
        float2 v1 = __half22float2(xwh[c1 * 32 + lane]);
        a0.x += v0.x; a0.y += v0.y;
        a1.x += v1.x; a1.y += v1.y;
    }
    if (e < m) {
        int c = sl[e];
        float2 v = __half22float2(xwh[c * 32 + lane]);
        a2.x += v.x; a2.y += v.y;
    }

    float inv = 1.f / ((float)deg + 1e-6f);
    float2 bb = ((const float2*)bias)[lane];
    float2 r;
    r.x = ((a0.x + a1.x) + (a2.x + a3.x)) * inv + bb.x;
    r.y = ((a0.y + a1.y) + (a2.y + a3.y)) * inv + bb.y;
    ((float2*)out)[(size_t)w * 32 + lane] = r;

    // Reset counter for the next graph replay. All lanes loaded g_cnt[w]
    // above; syncwarp orders those reads before lane 0's store.
    __syncwarp();
    if (lane == 0) g_cnt[w] = 0;
}

// ---------------------------------------------------------------------------
extern "C" void kernel_launch(void* const* d_in, const int* in_sizes, int n_in,
                              void* d_out, int out_size) {
    const float* x  = (const float*)d_in[0];
    const void*  ei = d_in[1];
    const float* W  = (const float*)d_in[2];
    const float* b  = (const float*)d_in[3];
    float*       out = (float*)d_out;

    int n  = in_sizes[0] / DIM;   // 50000
    int ne = in_sizes[1] / 2;     // 800000 (element count is 2E for both dtypes)

    prep_kernel<<<16, 256>>>(W, ei, ne, n);      // W transpose + dtype detect only

    int tblocks = (n + TM - 1) / TM;            // 391 transform blocks
    int fblocks = (ne + 255) / 256;             // 3125 fill blocks
    tf_kernel<<<tblocks + fblocks, 256>>>(x, ei, n, ne, tblocks);

    {
        long long thr = (long long)n * 32;
        gather_kernel<<<(int)((thr + 255) / 256), 256>>>(b, out, n);
    }
}